// round 4
// baseline (speedup 1.0000x reference)
#include <cuda_runtime.h>
#include <cuda_bf16.h>

#define NJ   32
#define TPB  384     // 128 batches x 3 matrix columns
#define BPB  128     // batches per block
#define IN_PAD  37   // 36 + 1 (odd stride -> conflict-free LDS/STS)
#define OUT_PAD 13   // 12 + 1

__global__ void __launch_bounds__(TPB, 4)
fk32_kernel(const float* __restrict__ angles,
            const float* __restrict__ offs,
            float* __restrict__ out,
            int batch)
{
    __shared__ float s_in [BPB * IN_PAD];   // 18,944 B
    __shared__ float s_out[BPB * OUT_PAD];  //  6,656 B

    const int tid = threadIdx.x;
    const int B0  = blockIdx.x * BPB;
    const int c   = tid / 3;        // batch-in-block 0..127
    const int l   = tid - c * 3;    // rotation-matrix column 0..2

    // H36M parent table; all FK indexing is compile-time after unroll.
    const int par[NJ] = {-1,0,1,2,3,4,0,6,7,8,9,0,11,12,13,14,12,16,17,18,
                         19,20,19,22,12,24,25,26,27,28,27,30};
    // Joints whose rotation is consumed by a child (leaves skip R update).
    const bool isp[NJ] = {1,1,1,1,1,0,1,1,1,1,0,1,1,1,1,0,
                          1,1,1,1,1,0,1,0,1,1,1,1,1,0,1,0};

    // Column-l FK state: Rc[j][k] = R[j][k][l], Pc[j] = P[j][l].
    // Constant indices -> scalarized; live set is tiny (~3 parent columns).
    float Rc[NJ][3];
    float Pc[NJ];

    const float* s_a = &s_in[c * IN_PAD];   // this thread's batch record

    #pragma unroll
    for (int g = 0; g < 8; ++g) {
        // ===== phase 1: coalesced GMEM -> SMEM (128 x 36 tile, scalar) =====
        #pragma unroll
        for (int k = 0; k < 12; ++k) {
            int idx = tid + k * TPB;          // 0..4607
            int cc  = idx / 36;
            int off = idx - cc * 36;
            int bb  = B0 + cc;
            if (bb >= batch) bb = batch - 1;
            s_in[cc * IN_PAD + off] = angles[(size_t)bb * 288 + g * 36 + off];
        }
        __syncthreads();

        // ===== phase 2: column-FK for joints 4g..4g+3 ======================
        #pragma unroll
        for (int jj = 0; jj < 4; ++jj) {
            const int j = g * 4 + jj;
            if (j == 0) {
                Rc[0][0] = s_a[0 * 3 + l];
                Rc[0][1] = s_a[1 * 3 + l];
                Rc[0][2] = s_a[2 * 3 + l];
                Pc[0]    = 0.f;
            } else {
                const int p = par[j];
                const float o0 = __ldg(&offs[j * 3 + 0]);
                const float o1 = __ldg(&offs[j * 3 + 1]);
                const float o2 = __ldg(&offs[j * 3 + 2]);
                Pc[j] = fmaf(o0, Rc[p][0],
                        fmaf(o1, Rc[p][1],
                        fmaf(o2, Rc[p][2], Pc[p])));
                if (isp[j]) {
                    #pragma unroll
                    for (int i = 0; i < 3; ++i) {
                        float a0 = s_a[jj * 9 + i * 3 + 0];
                        float a1 = s_a[jj * 9 + i * 3 + 1];
                        float a2 = s_a[jj * 9 + i * 3 + 2];
                        Rc[j][i] = fmaf(a0, Rc[p][0],
                                   fmaf(a1, Rc[p][1],
                                        a2 * Rc[p][2]));
                    }
                }
            }
            // each column thread owns its slot: no cross-thread races
            s_out[c * OUT_PAD + jj * 3 + l] = Pc[j];
        }
        __syncthreads();

        // ===== phase 3: coalesced SMEM -> GMEM (128 x 12 tile, scalar) =====
        // (phase1(g+1) writes s_in: all s_in readers passed the sync above;
        //  phase2(g+1) writes s_out only after the next post-phase1 sync.)
        #pragma unroll
        for (int k = 0; k < 4; ++k) {
            int idx = tid + k * TPB;          // 0..1535
            int cc  = idx / 12;
            int off = idx - cc * 12;
            int bb  = B0 + cc;
            if (bb < batch)
                out[(size_t)bb * 96 + g * 12 + off] = s_out[cc * OUT_PAD + off];
        }
    }
}

extern "C" void kernel_launch(void* const* d_in, const int* in_sizes, int n_in,
                              void* d_out, int out_size)
{
    const float* angles = (const float*)d_in[0];
    const float* offs   = (const float*)d_in[1];
    float* out          = (float*)d_out;

    int batch  = in_sizes[0] / (NJ * 9);            // 262144
    int blocks = (batch + BPB - 1) / BPB;           // 2048

    fk32_kernel<<<blocks, TPB>>>(angles, offs, out, batch);
}

// round 6
// speedup vs baseline: 2.7476x; 2.7476x over previous
#include <cuda_runtime.h>
#include <cuda_bf16.h>
#include <cstdint>

#define NJ    32
#define TPB   64
#define BPB   64                  // one batch per thread
#define RECW  292                 // 288 data floats + 4 pad (lane stride = 4 banks -> conflict-free LDS.128)
#define SMEM_BYTES (BPB * RECW * 4)   // 74,752 B

__device__ __forceinline__ void cp_async16(uint32_t s_addr, const void* g_ptr) {
    asm volatile("cp.async.cg.shared.global [%0], [%1], 16;\n"
                 :: "r"(s_addr), "l"(g_ptr));
}

__global__ void __launch_bounds__(TPB)
fk32_kernel(const float* __restrict__ angles,
            const float* __restrict__ offs,
            float* __restrict__ out,
            int batch)
{
    extern __shared__ float s[];          // BPB records of RECW floats

    const int t  = threadIdx.x;
    const int B0 = blockIdx.x * BPB;

    // ===== phase 1: one dense cp.async sweep, gmem side fully contiguous ====
    // block reads angles[B0 .. B0+63] = 4608 contiguous float4
    {
        const float4* srcv = reinterpret_cast<const float4*>(angles) + (size_t)B0 * 72;
        uint32_t sbase = (uint32_t)__cvta_generic_to_shared(s);
        #pragma unroll
        for (int k = 0; k < 72; ++k) {
            int q   = t + k * TPB;        // 0..4607
            int c   = q / 72;             // batch-in-block
            int off = q - c * 72;         // float4 within record
            // smem word addr: c*RECW + off*4  (16B aligned)
            cp_async16(sbase + (uint32_t)(c * RECW + off * 4) * 4u, srcv + q);
        }
        asm volatile("cp.async.commit_group;\n" ::: "memory");
        asm volatile("cp.async.wait_group 0;\n" ::: "memory");
    }
    __syncthreads();

    // ===== phase 2: per-thread full FK from own smem record ================
    {
        const int par[NJ] = {-1,0,1,2,3,4,0,6,7,8,9,0,11,12,13,14,12,16,17,18,
                             19,20,19,22,12,24,25,26,27,28,27,30};
        const bool isp[NJ] = {1,1,1,1,1,0,1,1,1,1,0,1,1,1,1,0,
                              1,1,1,1,1,0,1,0,1,1,1,1,1,0,1,0};

        float* rec = &s[t * RECW];
        float4* recv = reinterpret_cast<float4*>(rec);   // 16B aligned (RECW%4==0)

        float R[NJ][9];
        float P[NJ][3];

        #pragma unroll
        for (int g = 0; g < 8; ++g) {
            // 9 conflict-free LDS.128: this group's 4 rotation matrices
            float a[36];
            #pragma unroll
            for (int q = 0; q < 9; ++q) {
                float4 v = recv[g * 9 + q];
                a[4*q+0] = v.x; a[4*q+1] = v.y; a[4*q+2] = v.z; a[4*q+3] = v.w;
            }

            #pragma unroll
            for (int jj = 0; jj < 4; ++jj) {
                const int j = g * 4 + jj;
                const float* Aj = &a[jj * 9];
                if (j == 0) {
                    #pragma unroll
                    for (int q = 0; q < 9; ++q) R[0][q] = Aj[q];
                    P[0][0] = 0.f; P[0][1] = 0.f; P[0][2] = 0.f;
                } else {
                    const int p = par[j];
                    const float o0 = __ldg(&offs[j*3+0]);
                    const float o1 = __ldg(&offs[j*3+1]);
                    const float o2 = __ldg(&offs[j*3+2]);
                    #pragma unroll
                    for (int l = 0; l < 3; ++l) {
                        P[j][l] = fmaf(o0, R[p][0*3+l],
                                  fmaf(o1, R[p][1*3+l],
                                  fmaf(o2, R[p][2*3+l], P[p][l])));
                    }
                    if (isp[j]) {
                        #pragma unroll
                        for (int i = 0; i < 3; ++i) {
                            #pragma unroll
                            for (int l = 0; l < 3; ++l) {
                                R[j][i*3+l] = fmaf(Aj[i*3+0], R[p][0*3+l],
                                              fmaf(Aj[i*3+1], R[p][1*3+l],
                                                   Aj[i*3+2] * R[p][2*3+l]));
                            }
                        }
                    }
                }
            }

            // pack this group's 12 position floats -> 3 STS.128 into word
            // offset [12g, 12g+12) of own record. That range belongs to record
            // group floor(g/3) <= g, whose floats are already consumed (group
            // g itself was copied to regs above), so the slots are dead.
            const int j0 = g * 4;
            recv[g * 3 + 0] = make_float4(P[j0+0][0], P[j0+0][1], P[j0+0][2], P[j0+1][0]);
            recv[g * 3 + 1] = make_float4(P[j0+1][1], P[j0+1][2], P[j0+2][0], P[j0+2][1]);
            recv[g * 3 + 2] = make_float4(P[j0+2][2], P[j0+3][0], P[j0+3][1], P[j0+3][2]);
        }
    }
    __syncthreads();

    // ===== phase 3: coalesced float4 flush of positions ====================
    // positions live at words [0, 96) of each record -> out is written as
    // dense, full 128B lines (exactly 100 MB chip-wide).
    {
        float4* dstv = reinterpret_cast<float4*>(out) + (size_t)B0 * 24;
        const float4* sv = reinterpret_cast<const float4*>(s);
        #pragma unroll
        for (int k = 0; k < 24; ++k) {
            int q   = t + k * TPB;        // 0..1535
            int c   = q / 24;
            int off = q - c * 24;
            if (B0 + c < batch)
                dstv[q] = sv[(c * RECW) / 4 + off];
        }
    }
}

extern "C" void kernel_launch(void* const* d_in, const int* in_sizes, int n_in,
                              void* d_out, int out_size)
{
    const float* angles = (const float*)d_in[0];
    const float* offs   = (const float*)d_in[1];
    float* out          = (float*)d_out;

    int batch  = in_sizes[0] / (NJ * 9);          // 262144
    int blocks = (batch + BPB - 1) / BPB;         // 4096

    static bool attr_done = false;
    if (!attr_done) {
        cudaFuncSetAttribute(fk32_kernel,
                             cudaFuncAttributeMaxDynamicSharedMemorySize,
                             SMEM_BYTES);
        attr_done = true;
    }

    fk32_kernel<<<blocks, TPB, SMEM_BYTES>>>(angles, offs, out, batch);
}